// round 1
// baseline (speedup 1.0000x reference)
#include <cuda_runtime.h>
#include <math.h>

// Problem constants
#define Nn 100000
#define Ee 1600000
#define Ss 4
#define Dd 128
#define Hh 256
#define Pp 10000

#define SCAN_BLOCKS 98   // ceil(100000/1024)

// ---------------- scratch (device globals; no allocations) ----------------
__device__ float g_XW1[(size_t)Nn * Hh];   // X @ W1 (snapshot-invariant)
__device__ float g_H1 [(size_t)Nn * Hh];   // relu(layer-1 output)
__device__ float g_HW2[(size_t)Nn * Hh];   // H1 @ W2
__device__ float g_ACC[(size_t)Nn * Hh];   // snapshot accumulator
__device__ float g_DINV[Nn];
__device__ float g_NRM[Ee];                // per-CSR-slot edge norm
__device__ int   g_CNT[Nn];
__device__ int   g_ROWPTR[Nn + 1];
__device__ int   g_CURS[Nn];
__device__ int   g_COL[Ee];                // per-CSR-slot source node
__device__ int   g_BSUM[SCAN_BLOCKS];

// ---------------- SGEMM: C[M,256] = A[M,K] @ B[K,256] ----------------
// mode 0: A = param (node_features), C = g_XW1
// mode 1: A = g_H1,                  C = g_HW2
__global__ __launch_bounds__(256) void sgemm_kernel(
    const float* __restrict__ Ap, const float* __restrict__ B,
    int mode, int M, int K)
{
    const int BM = 128, BN = 128, BK = 16;
    __shared__ float As[BK][BM];
    __shared__ float Bs[BK][BN];

    const float* A = mode ? g_H1 : Ap;
    float*       C = mode ? g_HW2 : g_XW1;
    const int Ncol = Hh;

    int tid = threadIdx.x;                 // 256 threads
    int rowBase = blockIdx.x * BM;
    int colBase = blockIdx.y * BN;
    int tr = tid >> 4;                     // 0..15
    int tc = tid & 15;                     // 0..15

    float acc[8][8];
#pragma unroll
    for (int i = 0; i < 8; i++)
#pragma unroll
        for (int j = 0; j < 8; j++) acc[i][j] = 0.f;

    for (int k0 = 0; k0 < K; k0 += BK) {
        // A tile 128x16 = 512 float4 (2 per thread), stored transposed
#pragma unroll
        for (int l = 0; l < 2; l++) {
            int f = tid + l * 256;         // 0..511
            int r = f >> 2;                // tile row 0..127
            int cc = (f & 3) * 4;          // tile col 0,4,8,12
            float4 v = make_float4(0.f, 0.f, 0.f, 0.f);
            int gr = rowBase + r;
            if (gr < M)
                v = *reinterpret_cast<const float4*>(&A[(size_t)gr * K + k0 + cc]);
            As[cc + 0][r] = v.x; As[cc + 1][r] = v.y;
            As[cc + 2][r] = v.z; As[cc + 3][r] = v.w;
        }
        // B tile 16x128 = 512 float4 (2 per thread)
#pragma unroll
        for (int l = 0; l < 2; l++) {
            int f = tid + l * 256;
            int r = f >> 5;                // 0..15
            int cc = (f & 31) * 4;         // 0..124
            float4 v = *reinterpret_cast<const float4*>(
                &B[(size_t)(k0 + r) * Ncol + colBase + cc]);
            *reinterpret_cast<float4*>(&Bs[r][cc]) = v;
        }
        __syncthreads();

#pragma unroll
        for (int k = 0; k < BK; k++) {
            float ra[8], rb[8];
#pragma unroll
            for (int i = 0; i < 8; i++) ra[i] = As[k][tr * 8 + i];
#pragma unroll
            for (int j = 0; j < 8; j++) rb[j] = Bs[k][tc * 8 + j];
#pragma unroll
            for (int i = 0; i < 8; i++)
#pragma unroll
                for (int j = 0; j < 8; j++)
                    acc[i][j] = fmaf(ra[i], rb[j], acc[i][j]);
        }
        __syncthreads();
    }

#pragma unroll
    for (int i = 0; i < 8; i++) {
        int gr = rowBase + tr * 8 + i;
        if (gr < M) {
#pragma unroll
            for (int j = 0; j < 8; j += 4) {
                float4 v = make_float4(acc[i][j], acc[i][j + 1],
                                       acc[i][j + 2], acc[i][j + 3]);
                *reinterpret_cast<float4*>(
                    &C[(size_t)gr * Ncol + colBase + tc * 8 + j]) = v;
            }
        }
    }
}

// ---------------- CSR build ----------------
__global__ void zero_cnt_kernel() {
    int i = blockIdx.x * blockDim.x + threadIdx.x;
    if (i < Nn) g_CNT[i] = 0;
}

__global__ void count_kernel(const int* __restrict__ dst) {
    int e = blockIdx.x * blockDim.x + threadIdx.x;
    if (e < Ee) atomicAdd(&g_CNT[dst[e]], 1);
}

__global__ __launch_bounds__(1024) void scan1_kernel() {
    __shared__ int sh[1024];
    int i = blockIdx.x * 1024 + threadIdx.x;
    int v = (i < Nn) ? g_CNT[i] : 0;
    sh[threadIdx.x] = v;
    __syncthreads();
    for (int off = 1; off < 1024; off <<= 1) {
        int t = 0;
        if (threadIdx.x >= off) t = sh[threadIdx.x - off];
        __syncthreads();
        sh[threadIdx.x] += t;
        __syncthreads();
    }
    if (i < Nn) g_ROWPTR[i] = sh[threadIdx.x] - v;   // exclusive within block
    if (threadIdx.x == 1023) g_BSUM[blockIdx.x] = sh[1023];
}

__global__ void scan2_kernel(int nb) {
    if (threadIdx.x == 0 && blockIdx.x == 0) {
        int s = 0;
        for (int b = 0; b < nb; b++) { int t = g_BSUM[b]; g_BSUM[b] = s; s += t; }
    }
}

__global__ void scan3_kernel() {
    int i = blockIdx.x * blockDim.x + threadIdx.x;
    if (i < Nn) {
        int r = g_ROWPTR[i] + g_BSUM[i >> 10];
        g_ROWPTR[i] = r;
        g_CURS[i]   = r;
        g_DINV[i]   = rsqrtf((float)(g_CNT[i] + 1));
    }
    if (i == 0) g_ROWPTR[Nn] = Ee;
}

__global__ void fill_kernel(const int* __restrict__ src, const int* __restrict__ dst) {
    int e = blockIdx.x * blockDim.x + threadIdx.x;
    if (e < Ee) {
        int d = dst[e], s = src[e];
        int slot = atomicAdd(&g_CURS[d], 1);
        g_COL[slot] = s;
        g_NRM[slot] = g_DINV[s] * g_DINV[d];
    }
}

// ---------------- pull-based GCN aggregation ----------------
// layer 1: H1 = relu( sum_{e->i} XW1[src]*nrm + XW1[i]*dinv^2 + b1 )
__global__ __launch_bounds__(256) void pull_l1_kernel(const float* __restrict__ b1) {
    int warp = (blockIdx.x * blockDim.x + threadIdx.x) >> 5;
    int lane = threadIdx.x & 31;
    if (warp >= Nn) return;
    int i = warp;
    int beg = g_ROWPTR[i], end = g_ROWPTR[i + 1];
    const float4* XW = reinterpret_cast<const float4*>(g_XW1);

    float4 a0 = make_float4(0.f, 0.f, 0.f, 0.f);
    float4 a1 = make_float4(0.f, 0.f, 0.f, 0.f);

    int e = beg;
    for (; e + 1 < end; e += 2) {
        int s0 = g_COL[e],     s1 = g_COL[e + 1];
        float w0 = g_NRM[e],   w1 = g_NRM[e + 1];
        float4 v0 = XW[(size_t)s0 * 64 + lane];
        float4 v1 = XW[(size_t)s0 * 64 + 32 + lane];
        float4 u0 = XW[(size_t)s1 * 64 + lane];
        float4 u1 = XW[(size_t)s1 * 64 + 32 + lane];
        a0.x = fmaf(v0.x, w0, a0.x); a0.y = fmaf(v0.y, w0, a0.y);
        a0.z = fmaf(v0.z, w0, a0.z); a0.w = fmaf(v0.w, w0, a0.w);
        a1.x = fmaf(v1.x, w0, a1.x); a1.y = fmaf(v1.y, w0, a1.y);
        a1.z = fmaf(v1.z, w0, a1.z); a1.w = fmaf(v1.w, w0, a1.w);
        a0.x = fmaf(u0.x, w1, a0.x); a0.y = fmaf(u0.y, w1, a0.y);
        a0.z = fmaf(u0.z, w1, a0.z); a0.w = fmaf(u0.w, w1, a0.w);
        a1.x = fmaf(u1.x, w1, a1.x); a1.y = fmaf(u1.y, w1, a1.y);
        a1.z = fmaf(u1.z, w1, a1.z); a1.w = fmaf(u1.w, w1, a1.w);
    }
    if (e < end) {
        int s0 = g_COL[e]; float w0 = g_NRM[e];
        float4 v0 = XW[(size_t)s0 * 64 + lane];
        float4 v1 = XW[(size_t)s0 * 64 + 32 + lane];
        a0.x = fmaf(v0.x, w0, a0.x); a0.y = fmaf(v0.y, w0, a0.y);
        a0.z = fmaf(v0.z, w0, a0.z); a0.w = fmaf(v0.w, w0, a0.w);
        a1.x = fmaf(v1.x, w0, a1.x); a1.y = fmaf(v1.y, w0, a1.y);
        a1.z = fmaf(v1.z, w0, a1.z); a1.w = fmaf(v1.w, w0, a1.w);
    }

    float di = g_DINV[i];
    float d2 = di * di;
    float4 s0 = XW[(size_t)i * 64 + lane];
    float4 s1 = XW[(size_t)i * 64 + 32 + lane];
    const float4* Bv = reinterpret_cast<const float4*>(b1);
    float4 bb0 = Bv[lane], bb1 = Bv[32 + lane];

    float4 o0, o1;
    o0.x = fmaxf(fmaf(s0.x, d2, a0.x) + bb0.x, 0.f);
    o0.y = fmaxf(fmaf(s0.y, d2, a0.y) + bb0.y, 0.f);
    o0.z = fmaxf(fmaf(s0.z, d2, a0.z) + bb0.z, 0.f);
    o0.w = fmaxf(fmaf(s0.w, d2, a0.w) + bb0.w, 0.f);
    o1.x = fmaxf(fmaf(s1.x, d2, a1.x) + bb1.x, 0.f);
    o1.y = fmaxf(fmaf(s1.y, d2, a1.y) + bb1.y, 0.f);
    o1.z = fmaxf(fmaf(s1.z, d2, a1.z) + bb1.z, 0.f);
    o1.w = fmaxf(fmaf(s1.w, d2, a1.w) + bb1.w, 0.f);

    float4* H = reinterpret_cast<float4*>(g_H1);
    H[(size_t)i * 64 + lane]      = o0;
    H[(size_t)i * 64 + 32 + lane] = o1;
}

// layer 2 + residual + snapshot accumulate:
// ACC (=/+=) sum_{e->i} HW2[src]*nrm + HW2[i]*dinv^2 + b2 + H1[i]
__global__ __launch_bounds__(256) void pull_l2_kernel(const float* __restrict__ b2, int first) {
    int warp = (blockIdx.x * blockDim.x + threadIdx.x) >> 5;
    int lane = threadIdx.x & 31;
    if (warp >= Nn) return;
    int i = warp;
    int beg = g_ROWPTR[i], end = g_ROWPTR[i + 1];
    const float4* HW = reinterpret_cast<const float4*>(g_HW2);

    float4 a0 = make_float4(0.f, 0.f, 0.f, 0.f);
    float4 a1 = make_float4(0.f, 0.f, 0.f, 0.f);

    int e = beg;
    for (; e + 1 < end; e += 2) {
        int s0 = g_COL[e],   s1 = g_COL[e + 1];
        float w0 = g_NRM[e], w1 = g_NRM[e + 1];
        float4 v0 = HW[(size_t)s0 * 64 + lane];
        float4 v1 = HW[(size_t)s0 * 64 + 32 + lane];
        float4 u0 = HW[(size_t)s1 * 64 + lane];
        float4 u1 = HW[(size_t)s1 * 64 + 32 + lane];
        a0.x = fmaf(v0.x, w0, a0.x); a0.y = fmaf(v0.y, w0, a0.y);
        a0.z = fmaf(v0.z, w0, a0.z); a0.w = fmaf(v0.w, w0, a0.w);
        a1.x = fmaf(v1.x, w0, a1.x); a1.y = fmaf(v1.y, w0, a1.y);
        a1.z = fmaf(v1.z, w0, a1.z); a1.w = fmaf(v1.w, w0, a1.w);
        a0.x = fmaf(u0.x, w1, a0.x); a0.y = fmaf(u0.y, w1, a0.y);
        a0.z = fmaf(u0.z, w1, a0.z); a0.w = fmaf(u0.w, w1, a0.w);
        a1.x = fmaf(u1.x, w1, a1.x); a1.y = fmaf(u1.y, w1, a1.y);
        a1.z = fmaf(u1.z, w1, a1.z); a1.w = fmaf(u1.w, w1, a1.w);
    }
    if (e < end) {
        int s0 = g_COL[e]; float w0 = g_NRM[e];
        float4 v0 = HW[(size_t)s0 * 64 + lane];
        float4 v1 = HW[(size_t)s0 * 64 + 32 + lane];
        a0.x = fmaf(v0.x, w0, a0.x); a0.y = fmaf(v0.y, w0, a0.y);
        a0.z = fmaf(v0.z, w0, a0.z); a0.w = fmaf(v0.w, w0, a0.w);
        a1.x = fmaf(v1.x, w0, a1.x); a1.y = fmaf(v1.y, w0, a1.y);
        a1.z = fmaf(v1.z, w0, a1.z); a1.w = fmaf(v1.w, w0, a1.w);
    }

    float di = g_DINV[i];
    float d2 = di * di;
    float4 s0 = HW[(size_t)i * 64 + lane];
    float4 s1 = HW[(size_t)i * 64 + 32 + lane];
    const float4* Bv = reinterpret_cast<const float4*>(b2);
    float4 bb0 = Bv[lane], bb1 = Bv[32 + lane];
    const float4* H = reinterpret_cast<const float4*>(g_H1);
    float4 h0 = H[(size_t)i * 64 + lane];
    float4 h1 = H[(size_t)i * 64 + 32 + lane];

    float4 r0, r1;
    r0.x = fmaf(s0.x, d2, a0.x) + bb0.x + h0.x;
    r0.y = fmaf(s0.y, d2, a0.y) + bb0.y + h0.y;
    r0.z = fmaf(s0.z, d2, a0.z) + bb0.z + h0.z;
    r0.w = fmaf(s0.w, d2, a0.w) + bb0.w + h0.w;
    r1.x = fmaf(s1.x, d2, a1.x) + bb1.x + h1.x;
    r1.y = fmaf(s1.y, d2, a1.y) + bb1.y + h1.y;
    r1.z = fmaf(s1.z, d2, a1.z) + bb1.z + h1.z;
    r1.w = fmaf(s1.w, d2, a1.w) + bb1.w + h1.w;

    float4* ACC = reinterpret_cast<float4*>(g_ACC);
    size_t i0 = (size_t)i * 64 + lane;
    size_t i1 = (size_t)i * 64 + 32 + lane;
    if (first) {
        ACC[i0] = r0; ACC[i1] = r1;
    } else {
        float4 c0 = ACC[i0], c1 = ACC[i1];
        c0.x += r0.x; c0.y += r0.y; c0.z += r0.z; c0.w += r0.w;
        c1.x += r1.x; c1.y += r1.y; c1.z += r1.z; c1.w += r1.w;
        ACC[i0] = c0; ACC[i1] = c1;
    }
}

// ---------------- classifier: sigmoid(relu(post@Wc1+bc1)@Wc2+bc2) ----------------
__global__ __launch_bounds__(128) void classifier_kernel(
    const int* __restrict__ post_idx,
    const float* __restrict__ Wc1, const float* __restrict__ bc1,
    const float* __restrict__ Wc2, const float* __restrict__ bc2,
    float* __restrict__ out)
{
    __shared__ float post[Hh];
    __shared__ float red[128];
    int p = blockIdx.x;
    int t = threadIdx.x;                    // 128 threads
    int node = post_idx[p];
    const float* row = &g_ACC[(size_t)node * Hh];
    post[t]       = row[t]       * 0.25f;   // mean over S=4 snapshots
    post[t + 128] = row[t + 128] * 0.25f;
    __syncthreads();

    float acc = bc1[t];
#pragma unroll 8
    for (int j = 0; j < Hh; j++)
        acc = fmaf(post[j], Wc1[(size_t)j * 128 + t], acc);
    acc = fmaxf(acc, 0.f);
    float v = acc * Wc2[t];

    red[t] = v;
    __syncthreads();
    for (int off = 64; off > 0; off >>= 1) {
        if (t < off) red[t] += red[t + off];
        __syncthreads();
    }
    if (t == 0) {
        float lg = red[0] + bc2[0];
        out[p] = 1.f / (1.f + expf(-lg));
    }
}

// ---------------- launch ----------------
extern "C" void kernel_launch(void* const* d_in, const int* in_sizes, int n_in,
                              void* d_out, int out_size)
{
    const float* X        = (const float*)d_in[0];
    const int*   EI       = (const int*)  d_in[1];
    const int*   post_idx = (const int*)  d_in[2];
    const float* W1       = (const float*)d_in[3];
    const float* b1       = (const float*)d_in[4];
    const float* W2       = (const float*)d_in[5];
    const float* b2       = (const float*)d_in[6];
    const float* Wc1      = (const float*)d_in[7];
    const float* bc1      = (const float*)d_in[8];
    const float* Wc2      = (const float*)d_in[9];
    const float* bc2      = (const float*)d_in[10];
    float* out = (float*)d_out;

    dim3 gemm_grid((Nn + 127) / 128, Hh / 128);      // (782, 2)
    const int nblk_node = (Nn + 255) / 256;          // 391
    const int nblk_edge = Ee / 256;                  // 6250
    const int nblk_pull = (Nn + 7) / 8;              // 12500 (warp/node, 8 warps/blk)

    // snapshot-invariant: XW1 = X @ W1
    sgemm_kernel<<<gemm_grid, 256>>>(X, W1, 0, Nn, Dd);

    for (int s = 0; s < Ss; s++) {
        const int* src = EI + (size_t)s * 2 * Ee;
        const int* dst = src + Ee;

        zero_cnt_kernel<<<nblk_node, 256>>>();
        count_kernel<<<nblk_edge, 256>>>(dst);
        scan1_kernel<<<SCAN_BLOCKS, 1024>>>();
        scan2_kernel<<<1, 32>>>(SCAN_BLOCKS);
        scan3_kernel<<<nblk_node, 256>>>();
        fill_kernel<<<nblk_edge, 256>>>(src, dst);

        pull_l1_kernel<<<nblk_pull, 256>>>(b1);
        sgemm_kernel<<<gemm_grid, 256>>>(nullptr, W2, 1, Nn, Hh);
        pull_l2_kernel<<<nblk_pull, 256>>>(b2, s == 0 ? 1 : 0);
    }

    classifier_kernel<<<Pp, 128>>>(post_idx, Wc1, bc1, Wc2, bc2, out);
}